// round 13
// baseline (speedup 1.0000x reference)
#include <cuda_runtime.h>

// ---- static scratch (allocation-free; zero-initialized at module load) ----
#define MAX_BF    32768            // B*F faces
#define TS        16               // tile size in pixels
#define MAXTILES  1024             // B * (S/TS)^2  (2*256 = 512 used)
#define CAP       8192             // per-tile list capacity (>= F)
#define BATCH     32               // triangles staged per smem batch
#define TPW       4                // triangles per warp in binner (lane-parallel)
#define NSPLIT    4                // sub-CTAs cooperating on one tile

__device__ float4 g_triA[MAX_BF];  // (v1x, v1y, dY0, dX0)
__device__ float4 g_triB[MAX_BF];  // (v2x, v2y, dY1, dX1)
__device__ float4 g_triC[MAX_BF];  // (v0x, v0y, dY2, dX2)
__device__ int    g_cnt[MAXTILES];    // reset each run (raster)
__device__ int    g_full[MAXTILES];   // reset each run (raster)
__device__ int    g_done[MAXTILES];   // reset each run (raster)
__device__ unsigned int g_mask[MAXTILES * 8];  // 256-bit coverage per tile
__device__ int    g_bins[MAXTILES * CAP];

// Reference-identical projection of one vertex.
__device__ __forceinline__ float2 project_vert(const float* __restrict__ verts,
                                               const float* __restrict__ cams,
                                               int b, int vi) {
    float f  = cams[b * 3 + 0];
    float cx = cams[b * 3 + 1];
    float cy = cams[b * 3 + 2];
    float image_size = cams[1] * 2.0f;   // cams[0,1] * 2 per reference
    const float* p = verts + vi * 3;
    float x = p[0], y = p[1], z = p[2];
    float px = f * x / z + cx;
    float py = f * y / z + cy;
    return make_float2(px / image_size * 2.0f - 1.0f,
                       py / image_size * 2.0f - 1.0f);
}

struct TriBin {
    int   ok;
    int   tx0, ty0, tbase, sx, ntiles;
    float kx[3], ky[3], kc[3];
};

// Full per-triangle setup; also emits the raster coefficient records.
__device__ __forceinline__ TriBin tri_setup(const int* __restrict__ faces,
                                            const float* __restrict__ verts,
                                            const float* __restrict__ cams,
                                            int t, int V, int F, int S, int NT) {
    TriBin r; r.ok = 0;
    int b = t / F;
    const int* fv = faces + t * 3;
    float2 v0 = project_vert(verts, cams, b, b * V + fv[0]);
    float2 v1 = project_vert(verts, cams, b, b * V + fv[1]);
    float2 v2 = project_vert(verts, cams, b, b * V + fv[2]);
    float area = (v1.x - v0.x) * (v2.y - v0.y)
               - (v1.y - v0.y) * (v2.x - v0.x);
    if (!(fabsf(area) > 1e-12f)) return r;

    float minx = fminf(v0.x, fminf(v1.x, v2.x));
    float maxx = fmaxf(v0.x, fmaxf(v1.x, v2.x));
    float miny = fminf(v0.y, fminf(v1.y, v2.y));
    float maxy = fmaxf(v0.y, fmaxf(v1.y, v2.y));
    float half = 0.5f * (float)S;
    int x0 = max(0,     (int)floorf((minx + 1.0f) * half - 0.5f) - 1);
    int x1 = min(S - 1, (int)ceilf ((maxx + 1.0f) * half - 0.5f) + 1);
    int y0 = max(0,     (int)floorf((miny + 1.0f) * half - 0.5f) - 1);
    int y1 = min(S - 1, (int)ceilf ((maxy + 1.0f) * half - 0.5f) + 1);
    if (x1 < x0 || y1 < y0) return r;

    r.ok = 1;
    r.tx0 = x0 / TS; r.ty0 = y0 / TS;
    r.tbase = b * NT * NT;
    r.sx = x1 / TS - r.tx0 + 1;
    r.ntiles = r.sx * (y1 / TS - r.ty0 + 1);

    g_triA[t] = make_float4(v1.x, v1.y, v2.y - v1.y, v2.x - v1.x);
    g_triB[t] = make_float4(v2.x, v2.y, v0.y - v2.y, v0.x - v2.x);
    g_triC[t] = make_float4(v0.x, v0.y, v1.y - v0.y, v1.x - v0.x);

    float ss = area > 0.0f ? -1.0f : 1.0f;   // interior: ss*w >= 0
    float axv[3] = {v1.x, v2.x, v0.x};
    float ayv[3] = {v1.y, v2.y, v0.y};
    float dXv[3] = {v2.x - v1.x, v0.x - v2.x, v1.x - v0.x};
    float dYv[3] = {v2.y - v1.y, v0.y - v2.y, v1.y - v0.y};
#pragma unroll
    for (int e = 0; e < 3; e++) {
        r.kx[e] = ss * dYv[e];
        r.ky[e] = -ss * dXv[e];
        r.kc[e] = ss * (ayv[e] * dXv[e] - axv[e] * dYv[e]);
    }
    return r;
}

// Corner-based tile classification on broadcast scalars: 0 cull, 1 list, 2 full.
__device__ __forceinline__ int tile_class_s(
    const float* kx, const float* ky, const float* kc,
    int tx, int ty, float invS, float span)
{
    float cx0 = (2.0f * (float)(tx * TS) + 1.0f) * invS - 1.0f;
    float cy0 = (2.0f * (float)(ty * TS) + 1.0f) * invS - 1.0f;
    const float MARGIN = 1e-4f;
    bool full = true, cull = false;
#pragma unroll
    for (int e = 0; e < 3; e++) {
        float base = kx[e] * cx0 + ky[e] * cy0 + kc[e];
        float dxs = kx[e] * span, dys = ky[e] * span;
        float tmin = base + fminf(dxs, 0.0f) + fminf(dys, 0.0f);
        float tmax = base + fmaxf(dxs, 0.0f) + fmaxf(dys, 0.0f);
        full = full && (tmin >= MARGIN);
        cull = cull || (tmax <= -MARGIN);
    }
    return full ? 2 : (cull ? 0 : 1);
}

// Warp-parallel binning, lane-parallel setup (lane l < TPW owns triangle
// base+l). Phase 1: classify/count via shfl broadcast; phase 2: bitmask replay.
__global__ void __launch_bounds__(256)
bin_kernel(const int* __restrict__ faces, const float* __restrict__ verts,
           const float* __restrict__ cams, int B, int V, int F, int S, int NT) {
    __shared__ int s_cnt[MAXTILES];
    __shared__ int s_base[MAXTILES];
    for (int i = threadIdx.x; i < MAXTILES; i += 256) s_cnt[i] = 0;
    __syncthreads();

    int BF = B * F;
    int warpId = blockIdx.x * 8 + (threadIdx.x >> 5);
    int warpBase = warpId * TPW;
    int lane = threadIdx.x & 31;
    float invS = 1.0f / (float)S;
    float span = 30.0f * invS;   // ndc span between tile corner pixel centers
    const unsigned int FULLM = 0xFFFFFFFFu;

    TriBin mine; mine.ok = 0;
    if (lane < TPW && warpBase + lane < BF)
        mine = tri_setup(faces, verts, cams, warpBase + lane, V, F, S, NT);

    unsigned int lmask[TPW];     // bit i: tile (i*32+lane) of triangle k is "list"
    unsigned int lmeta[TPW];     // packed tx0|ty0<<5|sx<<10|tbase<<15
#pragma unroll
    for (int k = 0; k < TPW; k++) { lmask[k] = 0u; lmeta[k] = 0u; }

    // phase 1: classify + count + full flags
#pragma unroll
    for (int k = 0; k < TPW; k++) {
        if (warpBase + k >= BF) break;
        if (!__shfl_sync(FULLM, mine.ok, k)) continue;
        float kx[3], ky[3], kc[3];
#pragma unroll
        for (int e = 0; e < 3; e++) {
            kx[e] = __shfl_sync(FULLM, mine.kx[e], k);
            ky[e] = __shfl_sync(FULLM, mine.ky[e], k);
            kc[e] = __shfl_sync(FULLM, mine.kc[e], k);
        }
        int tx0    = __shfl_sync(FULLM, mine.tx0, k);
        int ty0    = __shfl_sync(FULLM, mine.ty0, k);
        int sx     = __shfl_sync(FULLM, mine.sx, k);
        int ntiles = __shfl_sync(FULLM, mine.ntiles, k);
        int tbase  = __shfl_sync(FULLM, mine.tbase, k);
        lmeta[k] = (unsigned int)tx0 | ((unsigned int)ty0 << 5)
                 | ((unsigned int)sx << 10) | ((unsigned int)tbase << 15);
        unsigned int m = 0u;
        for (int i = lane; i < ntiles; i += 32) {
            int tx = tx0 + (i % sx);
            int ty = ty0 + (i / sx);
            int tile = tbase + ty * NT + tx;
            int c = tile_class_s(kx, ky, kc, tx, ty, invS, span);
            if (c == 2)      g_full[tile] = 1;
            else if (c == 1) { m |= 1u << (i >> 5); atomicAdd(&s_cnt[tile], 1); }
        }
        lmask[k] = m;
    }
    __syncthreads();
    for (int i = threadIdx.x; i < MAXTILES; i += 256) {
        int c = s_cnt[i];
        s_base[i] = c ? atomicAdd(&g_cnt[i], c) : 0;
        s_cnt[i] = 0;
    }
    __syncthreads();
    // phase 2: replay bitmasks and scatter
#pragma unroll
    for (int k = 0; k < TPW; k++) {
        unsigned int m = lmask[k];
        if (!m) continue;
        int t = warpBase + k;
        unsigned int me = lmeta[k];
        int tx0   = me & 31;
        int ty0   = (me >> 5) & 31;
        int sx    = (me >> 10) & 31;
        int tbase = me >> 15;
        while (m) {
            int bit = __ffs(m) - 1;
            m &= m - 1;
            int i = (bit << 5) + lane;
            int tx = tx0 + (i % sx);
            int ty = ty0 + (i / sx);
            int tile = tbase + ty * NT + tx;
            int pos = s_base[tile] + atomicAdd(&s_cnt[tile], 1);
            g_bins[tile * CAP + pos] = t;
        }
    }
}

// NSPLIT sub-CTAs per tile, each scanning a strided quarter of the tile's
// list (byte-identical edge test, warp/CTA early exit). Small BATCH keeps the
// wasted staging minimal for sub-CTAs that cover quickly. Coverage merged via
// per-tile 256-bit mask; last arriving sub-CTA writes floats + resets state.
__global__ void __launch_bounds__(256)
raster_kernel(float* __restrict__ out, int S, int NT) {
    __shared__ float4 sA[BATCH], sB[BATCH], sC[BATCH];
    __shared__ int s_old;
    __shared__ unsigned int s_mask[8];

    int tile = blockIdx.x >> 2;
    int part = blockIdx.x & (NSPLIT - 1);
    int b   = tile / (NT * NT);
    int rem = tile - b * (NT * NT);
    int tyT = rem / NT, txT = rem - tyT * NT;
    int tid = threadIdx.x;
    int ix = txT * TS + (tid & (TS - 1));
    int iy = tyT * TS + (tid >> 4);
    float* dst = out + (b * S + iy) * S + ix;

    int n    = g_cnt[tile];
    int full = g_full[tile];

    const unsigned int FULLM = 0xFFFFFFFFu;
    bool cov = false;

    if (!full && n > 0) {
        int m = (n - part + NSPLIT - 1) / NSPLIT;   // my strided sublist length
        const int* list = g_bins + tile * CAP;
        float invS = 1.0f / (float)S;
        float px = (2.0f * (float)ix + 1.0f) * invS - 1.0f;
        float py = (2.0f * (float)iy + 1.0f) * invS - 1.0f;

        for (int k0 = 0; k0 < m; k0 += BATCH) {
            int cnt = min(BATCH, m - k0);
            // parallel staging: threads 0..31 -> A, 32..63 -> B, 64..95 -> C
            int role = tid >> 5;           // warp index
            int slot = tid & 31;
            if (role < 3 && slot < cnt) {
                int f = list[part + NSPLIT * (k0 + slot)];
                if      (role == 0) sA[slot] = g_triA[f];
                else if (role == 1) sB[slot] = g_triB[f];
                else                sC[slot] = g_triC[f];
            }
            __syncthreads();

            for (int kc = 0; kc < cnt && !__all_sync(FULLM, cov); kc += 8) {
                int ke = min(kc + 8, cnt);
                #pragma unroll 8
                for (int k = kc; k < ke; k++) {
                    float4 A  = sA[k];
                    float4 Bq = sB[k];
                    float4 C  = sC[k];
                    float w0 = (px - A.x)  * A.z  - (py - A.y)  * A.w;
                    float w1 = (px - Bq.x) * Bq.z - (py - Bq.y) * Bq.w;
                    float w2 = (px - C.x)  * C.z  - (py - C.y)  * C.w;
                    float wmin = fminf(w0, fminf(w1, w2));
                    float wmax = fmaxf(w0, fmaxf(w1, w2));
                    cov |= (wmin >= 0.0f) | (wmax <= 0.0f);
                }
            }
            if (__syncthreads_and((int)cov)) break;   // also guards smem reuse
        }
        // publish this sub-CTA's coverage bits
        unsigned int wm = __ballot_sync(FULLM, cov);
        if ((tid & 31) == 0 && wm)
            atomicOr(&g_mask[tile * 8 + (tid >> 5)], wm);
    }

    // arrival protocol: every sub-CTA arrives exactly once
    __threadfence();
    __syncthreads();                 // all atomicOrs of this CTA are issued
    if (tid == 0) s_old = atomicAdd(&g_done[tile], 1);
    __syncthreads();

    if (s_old == NSPLIT - 1) {       // last sub-CTA: combine, write, reset
        __threadfence();
        if (tid < 8) s_mask[tid] = atomicExch(&g_mask[tile * 8 + tid], 0u);
        __syncthreads();
        float val;
        if (full) val = 1.0f;
        else      val = ((s_mask[tid >> 5] >> (tid & 31)) & 1u) ? 1.0f : 0.0f;
        *dst = val;
        if (tid == 0) { g_done[tile] = 0; g_cnt[tile] = 0; g_full[tile] = 0; }
    }
}

extern "C" void kernel_launch(void* const* d_in, const int* in_sizes, int n_in,
                              void* d_out, int out_size) {
    const float* verts = (const float*)d_in[0];   // [B,V,3] fp32
    const int*   faces = (const int*)d_in[1];     // [B,F,3] int32
    const float* cams  = (const float*)d_in[2];   // [B,3]   fp32

    int B = in_sizes[2] / 3;
    int V = in_sizes[0] / (3 * B);
    int F = in_sizes[1] / (3 * B);
    int S = 256;
    {   // derive S from out_size (S*S = out_size/B, S a power of two)
        int ss = out_size / B;
        int s = 1;
        while (s * s < ss) s <<= 1;
        if (s * s == ss) S = s;
    }
    int NT = S / TS;

    float* out = (float*)d_out;

    int binCTAs = (B * F + 8 * TPW - 1) / (8 * TPW);   // 8 warps/CTA
    bin_kernel<<<binCTAs, 256>>>(faces, verts, cams, B, V, F, S, NT);
    raster_kernel<<<B * NT * NT * NSPLIT, 256>>>(out, S, NT);
}